// round 2
// baseline (speedup 1.0000x reference)
#include <cuda_runtime.h>
#include <math.h>
#include <stddef.h>

// Problem dims
#define TT 1024
#define BB 256
#define XDIM 64
#define HDIM 256
#define FDIM 256
#define MM (TT*BB)          // 262144 rows for all big GEMMs

// ---------------------------------------------------------------------------
// Scratch (no cudaMalloc allowed): two 256MB ping-pong buffers + Whh^T
// ---------------------------------------------------------------------------
__device__ float g_bufA[(size_t)MM * FDIM];   // 67,108,864 floats = 256 MB
__device__ float g_bufB[(size_t)MM * FDIM];   // 256 MB
__device__ float g_WhhT[HDIM * HDIM];         // 256 KB

// ---------------------------------------------------------------------------
// Tiled NT SGEMM: C[M,N] = act( A[M,K] @ B[N,K]^T + bias (+ bias2) )
// BM=128, BN=64, BK=16, 256 threads, 8x4 per-thread microtile.
// All our shapes divide the tiles exactly (M=262144, N in {256,64}, K in {256,64}).
// ---------------------------------------------------------------------------
__global__ __launch_bounds__(256) void gemm_nt_kernel(
    const float* __restrict__ A, const float* __restrict__ B,
    const float* __restrict__ bias, const float* __restrict__ bias2,
    float* __restrict__ C, int M, int N, int K, int act)
{
    __shared__ float As[16 * 128];   // [k][m]
    __shared__ float Bs[16 * 64];    // [k][n]

    const int tid = threadIdx.x;
    const int m0 = blockIdx.x * 128;
    const int n0 = blockIdx.y * 64;
    const int tx = tid & 15;         // n-dir: 16 * 4 = 64
    const int ty = tid >> 4;         // m-dir: 16 * 8 = 128

    float acc[8][4];
#pragma unroll
    for (int i = 0; i < 8; i++)
#pragma unroll
        for (int j = 0; j < 4; j++) acc[i][j] = 0.0f;

    const int lrow = tid >> 2;          // 0..63
    const int lkc  = (tid & 3) * 4;     // 0,4,8,12

    const int ktiles = K >> 4;
    for (int kt = 0; kt < ktiles; kt++) {
        const int k0 = kt << 4;
        // global loads (issued before the barrier to overlap)
        float4 a0 = *(const float4*)(A + (size_t)(m0 + lrow)      * K + k0 + lkc);
        float4 a1 = *(const float4*)(A + (size_t)(m0 + lrow + 64) * K + k0 + lkc);
        float4 b0 = *(const float4*)(B + (size_t)(n0 + lrow)      * K + k0 + lkc);

        __syncthreads();   // previous tile's compute done before overwrite
        As[(lkc + 0) * 128 + lrow] = a0.x;
        As[(lkc + 1) * 128 + lrow] = a0.y;
        As[(lkc + 2) * 128 + lrow] = a0.z;
        As[(lkc + 3) * 128 + lrow] = a0.w;
        As[(lkc + 0) * 128 + lrow + 64] = a1.x;
        As[(lkc + 1) * 128 + lrow + 64] = a1.y;
        As[(lkc + 2) * 128 + lrow + 64] = a1.z;
        As[(lkc + 3) * 128 + lrow + 64] = a1.w;
        Bs[(lkc + 0) * 64 + lrow] = b0.x;
        Bs[(lkc + 1) * 64 + lrow] = b0.y;
        Bs[(lkc + 2) * 64 + lrow] = b0.z;
        Bs[(lkc + 3) * 64 + lrow] = b0.w;
        __syncthreads();

#pragma unroll
        for (int kk = 0; kk < 16; kk++) {
            float av[8], bv[4];
            *(float4*)(av)     = *(const float4*)(As + kk * 128 + ty * 8);
            *(float4*)(av + 4) = *(const float4*)(As + kk * 128 + ty * 8 + 4);
            *(float4*)(bv)     = *(const float4*)(Bs + kk * 64 + tx * 4);
#pragma unroll
            for (int i = 0; i < 8; i++)
#pragma unroll
                for (int j = 0; j < 4; j++)
                    acc[i][j] = fmaf(av[i], bv[j], acc[i][j]);
        }
    }

    // epilogue: bias (+bias2), optional tanh, vectorized store
    float bv[4];
#pragma unroll
    for (int j = 0; j < 4; j++) {
        float b = bias[n0 + tx * 4 + j];
        if (bias2) b += bias2[n0 + tx * 4 + j];
        bv[j] = b;
    }
#pragma unroll
    for (int i = 0; i < 8; i++) {
        float4 o;
        o.x = acc[i][0] + bv[0];
        o.y = acc[i][1] + bv[1];
        o.z = acc[i][2] + bv[2];
        o.w = acc[i][3] + bv[3];
        if (act) {
            o.x = tanhf(o.x); o.y = tanhf(o.y);
            o.z = tanhf(o.z); o.w = tanhf(o.w);
        }
        *(float4*)(C + (size_t)(m0 + ty * 8 + i) * N + n0 + tx * 4) = o;
    }
}

// ---------------------------------------------------------------------------
// Whh [i][j] -> WhhT [j][i]  (once; coalesced read, strided write, 256KB)
// ---------------------------------------------------------------------------
__global__ void transpose256_kernel(const float* __restrict__ Whh,
                                    float* __restrict__ WhhT)
{
    int idx = blockIdx.x * 256 + threadIdx.x;   // grid 256 x 256 threads
    int i = idx >> 8, j = idx & 255;
    WhhT[j * 256 + i] = Whh[idx];
}

// ---------------------------------------------------------------------------
// Recurrence. 128 blocks x 256 threads; block owns 2 batch rows (independent!).
// Whh^T rows [0,192) live in smem (192KB), rows [192,256) stream from L2.
// 4-way j-split per block; partials reduced through smem.
// Per step: Hall[t] = h; h = (1-a)h + a*tanh(Z[t] + h@Whh^T).
// ---------------------------------------------------------------------------
#define RJS 192
#define RSM_FLOATS (RJS * 256 + 512 + 2048)
#define RSM_BYTES (RSM_FLOATS * 4)              // 206,848 B

__global__ __launch_bounds__(256, 1) void recurrence_kernel(
    const float* __restrict__ Z, const float* __restrict__ WhhT,
    float* __restrict__ Hall)
{
    extern __shared__ float sm[];
    float* Wsm  = sm;                 // [RJS][256]  (j-major, i contiguous)
    float* h_sm = sm + RJS * 256;     // [2][256]
    float* red  = h_sm + 512;         // [4][2][256]

    const int tid = threadIdx.x;
    const int b0 = blockIdx.x * 2;

    for (int idx = tid; idx < RJS * 256; idx += 256) Wsm[idx] = WhhT[idx];
    h_sm[tid] = 0.0f;
    h_sm[256 + tid] = 0.0f;
    __syncthreads();

    const int jg = tid >> 6;          // j-group 0..3
    const int il = tid & 63;          // i/4 lane -> i = il*4 .. il*4+3
    const float a_i = (tid < 86) ? 0.001f : (tid < 171) ? 0.01f : 0.1f;

    const float4* Wsm4 = (const float4*)Wsm;
    const float4* Wg4  = (const float4*)WhhT;

    for (int t = 0; t < TT; t++) {
        const float* Zt = Z + ((size_t)t * BB + b0) * HDIM;
        float*       Ht = Hall + ((size_t)t * BB + b0) * HDIM;

        // prefetch Z (used ~2000 cycles later), snapshot + record h
        float z0 = Zt[tid], z1 = Zt[256 + tid];
        float h0t = h_sm[tid], h1t = h_sm[256 + tid];
        Ht[tid] = h0t;
        Ht[256 + tid] = h1t;

        float4 acc0 = make_float4(0.f, 0.f, 0.f, 0.f);
        float4 acc1 = make_float4(0.f, 0.f, 0.f, 0.f);

        // smem-resident part of Whh^T: 48 j-rows for this group
#pragma unroll 4
        for (int jj = 0; jj < RJS / 4; jj++) {
            int j = jg * (RJS / 4) + jj;
            float4 w = Wsm4[j * 64 + il];
            float hh0 = h_sm[j], hh1 = h_sm[256 + j];
            acc0.x = fmaf(w.x, hh0, acc0.x);
            acc0.y = fmaf(w.y, hh0, acc0.y);
            acc0.z = fmaf(w.z, hh0, acc0.z);
            acc0.w = fmaf(w.w, hh0, acc0.w);
            acc1.x = fmaf(w.x, hh1, acc1.x);
            acc1.y = fmaf(w.y, hh1, acc1.y);
            acc1.z = fmaf(w.z, hh1, acc1.z);
            acc1.w = fmaf(w.w, hh1, acc1.w);
        }
        // L2-resident tail (64 hot KB shared by all blocks): 16 j-rows/group
#pragma unroll 4
        for (int jj = 0; jj < (256 - RJS) / 4; jj++) {
            int j = RJS + jg * ((256 - RJS) / 4) + jj;
            float4 w = Wg4[j * 64 + il];
            float hh0 = h_sm[j], hh1 = h_sm[256 + j];
            acc0.x = fmaf(w.x, hh0, acc0.x);
            acc0.y = fmaf(w.y, hh0, acc0.y);
            acc0.z = fmaf(w.z, hh0, acc0.z);
            acc0.w = fmaf(w.w, hh0, acc0.w);
            acc1.x = fmaf(w.x, hh1, acc1.x);
            acc1.y = fmaf(w.y, hh1, acc1.y);
            acc1.z = fmaf(w.z, hh1, acc1.z);
            acc1.w = fmaf(w.w, hh1, acc1.w);
        }

        ((float4*)red)[(jg * 2 + 0) * 64 + il] = acc0;
        ((float4*)red)[(jg * 2 + 1) * 64 + il] = acc1;
        __syncthreads();

        // reduce 4 j-groups; thread tid owns output unit i = tid for both b
        float s0 = red[tid] + red[512 + tid] + red[1024 + tid] + red[1536 + tid];
        float s1 = red[256 + tid] + red[768 + tid] + red[1280 + tid] + red[1792 + tid];

        float hr0 = tanhf(s0 + z0);
        float hr1 = tanhf(s1 + z1);
        float hn0 = fmaf(a_i, hr0 - h0t, h0t);   // (1-a)h + a*hr
        float hn1 = fmaf(a_i, hr1 - h1t, h1t);

        h_sm[tid] = hn0;          // thread writes only its own slot
        h_sm[256 + tid] = hn1;
        __syncthreads();          // publish h before next step's dot products
    }
}

// ---------------------------------------------------------------------------
// Launch: 6 GEMMs + transpose + recurrence, all graph-capturable.
// Input order (metadata): x,Wx0,bx0,Wx1,bx1,Wih,Whh,bih,bhh,Wh0,bh0,Wh1,bh1,Wg,bg
// ---------------------------------------------------------------------------
extern "C" void kernel_launch(void* const* d_in, const int* in_sizes, int n_in,
                              void* d_out, int out_size)
{
    const float* x   = (const float*)d_in[0];
    const float* Wx0 = (const float*)d_in[1];
    const float* bx0 = (const float*)d_in[2];
    const float* Wx1 = (const float*)d_in[3];
    const float* bx1 = (const float*)d_in[4];
    const float* Wih = (const float*)d_in[5];
    const float* Whh = (const float*)d_in[6];
    const float* bih = (const float*)d_in[7];
    const float* bhh = (const float*)d_in[8];
    const float* Wh0 = (const float*)d_in[9];
    const float* bh0 = (const float*)d_in[10];
    const float* Wh1 = (const float*)d_in[11];
    const float* bh1 = (const float*)d_in[12];
    const float* Wg  = (const float*)d_in[13];
    const float* bg  = (const float*)d_in[14];
    float* y = (float*)d_out;

    float *bufA, *bufB, *whhT;
    cudaGetSymbolAddress((void**)&bufA, g_bufA);
    cudaGetSymbolAddress((void**)&bufB, g_bufB);
    cudaGetSymbolAddress((void**)&whhT, g_WhhT);

    cudaFuncSetAttribute(recurrence_kernel,
                         cudaFuncAttributeMaxDynamicSharedMemorySize, RSM_BYTES);

    dim3 blk(256);
    dim3 gN256(MM / 128, FDIM / 64);   // N=256 -> (2048, 4)
    dim3 gN64 (MM / 128, XDIM / 64);   // N=64  -> (2048, 1)

    // Whh^T (once per launch; cheap)
    transpose256_kernel<<<256, 256>>>(Whh, whhT);

    // feat1 = tanh(x @ Wx0^T + bx0)              [M,64]x[256,64]^T
    gemm_nt_kernel<<<gN256, blk>>>(x, Wx0, bx0, nullptr, bufA,
                                   MM, FDIM, XDIM, 1);
    // feat2 = tanh(feat1 @ Wx1^T + bx1)
    gemm_nt_kernel<<<gN256, blk>>>(bufA, Wx1, bx1, nullptr, bufB,
                                   MM, FDIM, FDIM, 1);
    // Z = feat2 @ Wih^T + bih + bhh   (no act)
    gemm_nt_kernel<<<gN256, blk>>>(bufB, Wih, bih, bhh, bufA,
                                   MM, HDIM, FDIM, 0);
    // sequential scan: Hall[t] = h_t ; h update   (Z in bufA, Hall -> bufB)
    recurrence_kernel<<<BB / 2, blk, RSM_BYTES>>>(bufA, whhT, bufB);
    // d1 = tanh(Hall @ Wh0^T + bh0)
    gemm_nt_kernel<<<gN256, blk>>>(bufB, Wh0, bh0, nullptr, bufA,
                                   MM, FDIM, HDIM, 1);
    // d2 = tanh(d1 @ Wh1^T + bh1)
    gemm_nt_kernel<<<gN256, blk>>>(bufA, Wh1, bh1, nullptr, bufB,
                                   MM, FDIM, FDIM, 1);
    // y = d2 @ Wg^T + bg
    gemm_nt_kernel<<<gN64, blk>>>(bufB, Wg, bg, nullptr, y,
                                  MM, XDIM, FDIM, 0);
}

// round 3
// speedup vs baseline: 1.4509x; 1.4509x over previous
#include <cuda_runtime.h>
#include <math.h>
#include <stddef.h>
#include <stdint.h>

// Problem dims
#define TT 1024
#define BB 256
#define XDIM 64
#define HDIM 256
#define FDIM 256
#define MM (TT*BB)          // 262144 rows for all big GEMMs

// ---------------------------------------------------------------------------
// Scratch (no cudaMalloc allowed)
// ---------------------------------------------------------------------------
__device__ float g_bufA[(size_t)MM * FDIM];   // 256 MB
__device__ float g_bufB[(size_t)MM * FDIM];   // 256 MB
__device__ float g_WhhT[HDIM * HDIM];         // 256 KB

// ---------------------------------------------------------------------------
// helpers
// ---------------------------------------------------------------------------
__device__ __forceinline__ uint32_t f2tf32(float x) {
    uint32_t u;
    asm("cvt.rna.tf32.f32 %0, %1;" : "=r"(u) : "f"(x));
    return u;
}

#define MMA_TF32(c, a, b)                                                   \
    asm volatile("mma.sync.aligned.m16n8k8.row.col.f32.tf32.tf32.f32 "      \
                 "{%0,%1,%2,%3}, {%4,%5,%6,%7}, {%8,%9}, {%0,%1,%2,%3};"    \
                 : "+f"(c[0]), "+f"(c[1]), "+f"(c[2]), "+f"(c[3])           \
                 : "r"(a.x), "r"(a.y), "r"(a.z), "r"(a.w),                  \
                   "r"(b.x), "r"(b.y))

#define FMA2(d, a, b)                                                       \
    asm("fma.rn.f32x2 %0, %1, %2, %0;" : "+l"(d) : "l"(a), "l"(b))

__device__ __forceinline__ unsigned long long packf2(float f) {
    unsigned long long d;
    uint32_t u = __float_as_uint(f);
    asm("mov.b64 %0, {%1, %1};" : "=l"(d) : "r"(u));
    return d;
}

// ---------------------------------------------------------------------------
// tf32 tensor-core GEMM: C[M,N] = act( A[M,K] @ B[N,K]^T + bias (+bias2) )
// BM=128 fixed, BK=32, 256 threads (8 warps). Warp tile = (WM_AT*16) x (WN_AT*8).
// Fragment-shuffled smem: A stored as [s][m_atom][lane]{4 x u32},
// B as [s][n_atom][lane]{2 x u32}; fragment reads are clean LDS.128 / LDS.64.
// m16n8k8 lane mapping: g = lane>>2, tig = lane&3.
//   a0=A[g][tig] a1=A[g+8][tig] a2=A[g][tig+4] a3=A[g+8][tig+4]
//   b0=B[k=tig][n=g] b1=B[k=tig+4][n=g]   (B[k][n] = W[n][k], so D = A @ W^T)
//   c0=C[g][2t] c1=C[g][2t+1] c2=C[g+8][2t] c3=C[g+8][2t+1]
// ---------------------------------------------------------------------------
template<int WARPS_M, int WARPS_N, int WM_AT, int WN_AT, int BN>
__global__ __launch_bounds__(256) void gemm_tf32_kernel(
    const float* __restrict__ A, const float* __restrict__ B,
    const float* __restrict__ bias, const float* __restrict__ bias2,
    float* __restrict__ C, int M, int N, int K, int act)
{
    constexpr int BM = 128;
    constexpr int NATB = BN / 8;          // B atoms per k8-slice
    constexpr int BIT_A = (BM * 8) / 256; // A float4s per thread per BK tile (4)
    constexpr int BIT_B = (BN * 8) / 256; // B float4s per thread per BK tile

    __shared__ __align__(16) uint32_t As[4 * 8 * 32 * 4];     // 16 KB
    __shared__ __align__(16) uint32_t Bs[4 * NATB * 32 * 2];  // <= 16 KB

    const int tid  = threadIdx.x;
    const int warp = tid >> 5;
    const int lane = tid & 31;
    const int wm   = warp / WARPS_N;
    const int wn   = warp % WARPS_N;
    const int m0   = blockIdx.y * BM;
    const int n0   = blockIdx.x * BN;

    float c[WM_AT][WN_AT][4];
#pragma unroll
    for (int mi = 0; mi < WM_AT; mi++)
#pragma unroll
        for (int ni = 0; ni < WN_AT; ni++)
#pragma unroll
            for (int e = 0; e < 4; e++) c[mi][ni][e] = 0.0f;

    const uint4* As4 = (const uint4*)As;
    const uint2* Bs2 = (const uint2*)Bs;

    for (int kt = 0; kt < K; kt += 32) {
        float4 aL[BIT_A];
        float4 bL[BIT_B];
#pragma unroll
        for (int it = 0; it < BIT_A; it++) {
            int idx = tid + it * 256;
            int row = idx >> 3, c0 = (idx & 7) * 4;
            aL[it] = *(const float4*)(A + (size_t)(m0 + row) * K + kt + c0);
        }
#pragma unroll
        for (int it = 0; it < BIT_B; it++) {
            int idx = tid + it * 256;
            int row = idx >> 3, c0 = (idx & 7) * 4;
            bL[it] = *(const float4*)(B + (size_t)(n0 + row) * K + kt + c0);
        }

        __syncthreads();   // previous tile's compute finished

        // scatter-store A in fragment order (with tf32 rounding)
#pragma unroll
        for (int it = 0; it < BIT_A; it++) {
            int idx = tid + it * 256;
            int row = idx >> 3, c0 = (idx & 7) * 4;
            int s = c0 >> 3, e1 = (c0 >> 2) & 1;
            int a = row >> 4, g = row & 7, e0 = (row >> 3) & 1;
            int base = (s * 8 + a) * 32 + g * 4;
            float v[4]; *(float4*)v = aL[it];
#pragma unroll
            for (int j = 0; j < 4; j++)
                As[(base + j) * 4 + e0 + 2 * e1] = f2tf32(v[j]);
        }
        // scatter-store B in fragment order
#pragma unroll
        for (int it = 0; it < BIT_B; it++) {
            int idx = tid + it * 256;
            int row = idx >> 3, c0 = (idx & 7) * 4;
            int s = c0 >> 3, r = (c0 >> 2) & 1;
            int atom = row >> 3, g = row & 7;
            int base = (s * NATB + atom) * 32 + g * 4;
            float v[4]; *(float4*)v = bL[it];
#pragma unroll
            for (int j = 0; j < 4; j++)
                Bs[(base + j) * 2 + r] = f2tf32(v[j]);
        }
        __syncthreads();

#pragma unroll
        for (int s = 0; s < 4; s++) {
            uint4 af[WM_AT];
            uint2 bf[WN_AT];
#pragma unroll
            for (int mi = 0; mi < WM_AT; mi++)
                af[mi] = As4[(s * 8 + wm * WM_AT + mi) * 32 + lane];
#pragma unroll
            for (int ni = 0; ni < WN_AT; ni++)
                bf[ni] = Bs2[(s * NATB + wn * WN_AT + ni) * 32 + lane];
#pragma unroll
            for (int mi = 0; mi < WM_AT; mi++)
#pragma unroll
                for (int ni = 0; ni < WN_AT; ni++)
                    MMA_TF32(c[mi][ni], af[mi], bf[ni]);
        }
    }

    // epilogue: bias (+bias2), optional tanh
    const int g = lane >> 2, tig = lane & 3;
#pragma unroll
    for (int mi = 0; mi < WM_AT; mi++) {
        int r0 = m0 + (wm * WM_AT + mi) * 16 + g;
#pragma unroll
        for (int ni = 0; ni < WN_AT; ni++) {
            int cc = n0 + (wn * WN_AT + ni) * 8 + 2 * tig;
            float b0v = bias[cc], b1v = bias[cc + 1];
            if (bias2) { b0v += bias2[cc]; b1v += bias2[cc + 1]; }
            float v0 = c[mi][ni][0] + b0v;
            float v1 = c[mi][ni][1] + b1v;
            float v2 = c[mi][ni][2] + b0v;
            float v3 = c[mi][ni][3] + b1v;
            if (act) {
                v0 = tanhf(v0); v1 = tanhf(v1);
                v2 = tanhf(v2); v3 = tanhf(v3);
            }
            float2 lo = make_float2(v0, v1);
            float2 hi = make_float2(v2, v3);
            *(float2*)(C + (size_t)r0 * N + cc)       = lo;
            *(float2*)(C + (size_t)(r0 + 8) * N + cc) = hi;
        }
    }
}

// ---------------------------------------------------------------------------
// Whh [i][j] -> WhhT [j][i]
// ---------------------------------------------------------------------------
__global__ void transpose256_kernel(const float* __restrict__ Whh,
                                    float* __restrict__ WhhT)
{
    int idx = blockIdx.x * 256 + threadIdx.x;
    int i = idx >> 8, j = idx & 255;
    WhhT[j * 256 + i] = Whh[idx];
}

// ---------------------------------------------------------------------------
// Recurrence v2. 128 blocks x 256 threads, 2 batch rows per block.
// Thread (jg = tid>>6, il = tid&63) owns j-rows [jg*64, jg*64+64) and
// i-columns [il*4, il*4+4). W rows jg*64..+31 live in REGISTERS (128 regs),
// rows jg*64+32..+63 in smem (128 KB). FMA uses packed fma.rn.f32x2 over
// (i, i+1) pairs; h broadcast as pre-packed (h,h) f32x2 pairs via LDS.64.
// ---------------------------------------------------------------------------
#define R_SMEM_BYTES (128*256*4 + 2*256*8 + 2*4*256*4)   // 143,360 B

__global__ __launch_bounds__(256, 1) void recurrence2_kernel(
    const float* __restrict__ Z, const float* __restrict__ WhhT,
    float* __restrict__ Hall)
{
    extern __shared__ float sm[];
    float* Wsm = sm;                                            // 32768 floats
    unsigned long long* hd0 = (unsigned long long*)(Wsm + 32768);  // 256 ull
    unsigned long long* hd1 = hd0 + 256;                           // 256 ull
    float* red0 = (float*)(hd1 + 256);                             // [4][256]
    float* red1 = red0 + 1024;                                     // [4][256]

    const int tid = threadIdx.x;
    const int b0 = blockIdx.x * 2;
    const int jg = tid >> 6;
    const int il = tid & 63;

    // smem half of W: for each group jg, rows jg*64+32 .. jg*64+63
    for (int idx = tid; idx < 128 * 256; idx += 256) {
        int row = idx >> 8;                  // 0..127
        int jgs = row >> 5, rr = row & 31;
        Wsm[idx] = WhhT[(jgs * 64 + 32 + rr) * 256 + (idx & 255)];
    }
    // register half of W: rows jg*64 .. jg*64+31, cols il*4..il*4+3
    unsigned long long wlo[32], whi[32];
    {
        const ulonglong2* Wg = (const ulonglong2*)WhhT;   // 64 ull2 per row
        #pragma unroll
        for (int rr = 0; rr < 32; rr++) {
            ulonglong2 w = Wg[(jg * 64 + rr) * 64 + il];
            wlo[rr] = w.x;  whi[rr] = w.y;
        }
    }
    hd0[tid] = 0ULL;
    hd1[tid] = 0ULL;
    float h0t = 0.0f, h1t = 0.0f;
    const float a_i = (tid < 86) ? 0.001f : (tid < 171) ? 0.01f : 0.1f;
    __syncthreads();

    const ulonglong2* hd0p = (const ulonglong2*)hd0;
    const ulonglong2* hd1p = (const ulonglong2*)hd1;
    const ulonglong2* Wsm2 = (const ulonglong2*)Wsm;      // 64 ull2 per row

    for (int t = 0; t < TT; t++) {
        const float* Zt = Z + ((size_t)t * BB + b0) * HDIM;
        float*       Ht = Hall + ((size_t)t * BB + b0) * HDIM;

        float z0 = Zt[tid], z1 = Zt[256 + tid];
        Ht[tid] = h0t;
        Ht[256 + tid] = h1t;

        unsigned long long a00 = 0ULL, a01 = 0ULL, a10 = 0ULL, a11 = 0ULL;

        // register-resident W rows (j = jg*64 + 2*rp, +1)
        #pragma unroll
        for (int rp = 0; rp < 16; rp++) {
            ulonglong2 h0p = hd0p[jg * 32 + rp];
            ulonglong2 h1p = hd1p[jg * 32 + rp];
            FMA2(a00, wlo[2*rp],   h0p.x);  FMA2(a01, whi[2*rp],   h0p.x);
            FMA2(a10, wlo[2*rp],   h1p.x);  FMA2(a11, whi[2*rp],   h1p.x);
            FMA2(a00, wlo[2*rp+1], h0p.y);  FMA2(a01, whi[2*rp+1], h0p.y);
            FMA2(a10, wlo[2*rp+1], h1p.y);  FMA2(a11, whi[2*rp+1], h1p.y);
        }
        // smem-resident W rows (j = jg*64 + 32 + 2*rp, +1)
        #pragma unroll
        for (int rp = 0; rp < 16; rp++) {
            ulonglong2 h0p = hd0p[jg * 32 + 16 + rp];
            ulonglong2 h1p = hd1p[jg * 32 + 16 + rp];
            ulonglong2 w0 = Wsm2[(jg * 32 + 2*rp)     * 64 + il];
            ulonglong2 w1 = Wsm2[(jg * 32 + 2*rp + 1) * 64 + il];
            FMA2(a00, w0.x, h0p.x);  FMA2(a01, w0.y, h0p.x);
            FMA2(a10, w0.x, h1p.x);  FMA2(a11, w0.y, h1p.x);
            FMA2(a00, w1.x, h0p.y);  FMA2(a01, w1.y, h0p.y);
            FMA2(a10, w1.x, h1p.y);  FMA2(a11, w1.y, h1p.y);
        }

        // j-group partials -> smem
        {
            ulonglong2 r0; r0.x = a00; r0.y = a01;
            ulonglong2 r1; r1.x = a10; r1.y = a11;
            ((ulonglong2*)red0)[jg * 64 + il] = r0;
            ((ulonglong2*)red1)[jg * 64 + il] = r1;
        }
        __syncthreads();

        // reduce over 4 j-groups; thread tid owns output unit i = tid
        float s0 = red0[tid] + red0[256 + tid] + red0[512 + tid] + red0[768 + tid];
        float s1 = red1[tid] + red1[256 + tid] + red1[512 + tid] + red1[768 + tid];

        float hr0 = tanhf(s0 + z0);
        float hr1 = tanhf(s1 + z1);
        h0t = fmaf(a_i, hr0 - h0t, h0t);
        h1t = fmaf(a_i, hr1 - h1t, h1t);

        hd0[tid] = packf2(h0t);
        hd1[tid] = packf2(h1t);
        __syncthreads();     // publish h (and protect red) before next step
    }
}

// ---------------------------------------------------------------------------
// Launch. Input order: x,Wx0,bx0,Wx1,bx1,Wih,Whh,bih,bhh,Wh0,bh0,Wh1,bh1,Wg,bg
// ---------------------------------------------------------------------------
extern "C" void kernel_launch(void* const* d_in, const int* in_sizes, int n_in,
                              void* d_out, int out_size)
{
    const float* x   = (const float*)d_in[0];
    const float* Wx0 = (const float*)d_in[1];
    const float* bx0 = (const float*)d_in[2];
    const float* Wx1 = (const float*)d_in[3];
    const float* bx1 = (const float*)d_in[4];
    const float* Wih = (const float*)d_in[5];
    const float* Whh = (const float*)d_in[6];
    const float* bih = (const float*)d_in[7];
    const float* bhh = (const float*)d_in[8];
    const float* Wh0 = (const float*)d_in[9];
    const float* bh0 = (const float*)d_in[10];
    const float* Wh1 = (const float*)d_in[11];
    const float* bh1 = (const float*)d_in[12];
    const float* Wg  = (const float*)d_in[13];
    const float* bg  = (const float*)d_in[14];
    float* y = (float*)d_out;

    float *bufA, *bufB, *whhT;
    cudaGetSymbolAddress((void**)&bufA, g_bufA);
    cudaGetSymbolAddress((void**)&bufB, g_bufB);
    cudaGetSymbolAddress((void**)&whhT, g_WhhT);

    cudaFuncSetAttribute(recurrence2_kernel,
                         cudaFuncAttributeMaxDynamicSharedMemorySize, R_SMEM_BYTES);

    dim3 blk(256);
    // grid.x = N-tiles (fast-varying -> A tiles reused in L2), grid.y = M-tiles
    dim3 gN256(FDIM / 128, MM / 128);   // (2, 2048)
    dim3 gN64 (1,          MM / 128);   // (1, 2048)

    transpose256_kernel<<<256, 256>>>(Whh, whhT);

    // feat1 = tanh(x @ Wx0^T + bx0)       [M,64] x [256,64]^T
    gemm_tf32_kernel<2,4,4,4,128><<<gN256, blk>>>(x, Wx0, bx0, nullptr, bufA,
                                                  MM, FDIM, XDIM, 1);
    // feat2 = tanh(feat1 @ Wx1^T + bx1)
    gemm_tf32_kernel<2,4,4,4,128><<<gN256, blk>>>(bufA, Wx1, bx1, nullptr, bufB,
                                                  MM, FDIM, FDIM, 1);
    // Z = feat2 @ Wih^T + bih + bhh
    gemm_tf32_kernel<2,4,4,4,128><<<gN256, blk>>>(bufB, Wih, bih, bhh, bufA,
                                                  MM, HDIM, FDIM, 0);
    // sequential scan: Hall[t] = h_t ; h update  (Z in bufA, Hall -> bufB)
    recurrence2_kernel<<<BB / 2, blk, R_SMEM_BYTES>>>(bufA, whhT, bufB);
    // d1 = tanh(Hall @ Wh0^T + bh0)
    gemm_tf32_kernel<2,4,4,4,128><<<gN256, blk>>>(bufB, Wh0, bh0, nullptr, bufA,
                                                  MM, FDIM, HDIM, 1);
    // d2 = tanh(d1 @ Wh1^T + bh1)
    gemm_tf32_kernel<2,4,4,4,128><<<gN256, blk>>>(bufA, Wh1, bh1, nullptr, bufB,
                                                  MM, FDIM, FDIM, 1);
    // y = d2 @ Wg^T + bg
    gemm_tf32_kernel<4,2,2,4,64><<<gN64, blk>>>(bufB, Wg, bg, nullptr, y,
                                                MM, XDIM, FDIM, 0);
}